// round 16
// baseline (speedup 1.0000x reference)
#include <cuda_runtime.h>
#include <cuda_fp16.h>
#include <math.h>
#include <stdint.h>

// ---------------- problem constants ----------------
constexpr int CB   = 8;
constexpr int CN   = 1024;
constexpr int CM   = 8;
constexpr int CDIN = 1024;
constexpr int CHID = 256;
constexpr int CL   = 2;
constexpr int CNC  = 7;
constexpr int CDH  = 64;
#define NEGF  (-9e15f)
#define ALPHAF 0.1f
#define L2EF  1.4426950408889634f

// ---------------- scratch ----------------
__device__ float  g_H   [CB*CN*CHID];
__device__ float  g_Hn  [CB*CN*CHID];
__device__ float  g_P   [CB*CM*CHID];
__device__ float  g_PW  [CB*CM*CHID];
__device__ float  g_PaggP[4*CB*CM*CHID];
__device__ float  g_Agg [CB*CN*CHID];
__device__ float  g_ctx [CB*CN*CHID];
__device__ float  g_T   [CB*CN*CHID];
__device__ __align__(16) __half g_Qh  [CB*CN*CHID];
__device__ __align__(16) __half g_Kh  [CB*CN*CHID];
__device__ __align__(16) __half g_VT  [CB*CN*CHID];   // [bh][d][j]
__device__ __align__(16) __half g_hT  [CB*CN*CHID];   // [b][c][n]
__device__ __align__(16) __half g_WT8 [8*CHID*CHID];  // fp16 [N][K] weights
__device__ __align__(16) __half g_WTfc1[CHID*CDIN];   // fc1w^T fp16 [256][1024]
__device__ uint8_t g_codes[(long)CB*CN*CN];
__device__ float  g_e1  [CB*CN];
__device__ float  g_e2  [CB*CN];
__device__ float  g_rsc [2];

// ---------------- helpers ----------------
__device__ __forceinline__ void mma_f16(float c[4], const uint32_t a[4], const uint32_t b[2]) {
    asm volatile(
        "mma.sync.aligned.m16n8k16.row.col.f32.f16.f16.f32 "
        "{%0,%1,%2,%3}, {%4,%5,%6,%7}, {%8,%9}, {%0,%1,%2,%3};\n"
        : "+f"(c[0]), "+f"(c[1]), "+f"(c[2]), "+f"(c[3])
        : "r"(a[0]), "r"(a[1]), "r"(a[2]), "r"(a[3]), "r"(b[0]), "r"(b[1]));
}
__device__ __forceinline__ uint32_t pkh2(float x, float y) {
    __half2 h = __floats2half2_rn(x, y);
    return *(uint32_t*)&h;
}
__device__ __forceinline__ uint32_t ex2h2(float x, float y) {
    __half2 h = __floats2half2_rn(x, y);
    uint32_t r;
    asm("ex2.approx.f16x2 %0, %1;" : "=r"(r) : "r"(*(uint32_t*)&h));
    return r;
}
__device__ __forceinline__ void cpasync16(uint32_t saddr, const void* gptr) {
    asm volatile("cp.async.cg.shared.global [%0], [%1], 16;\n" :: "r"(saddr), "l"(gptr));
}
__device__ __forceinline__ void cpcommit() { asm volatile("cp.async.commit_group;\n"); }
__device__ __forceinline__ void cpwait0()  { asm volatile("cp.async.wait_group 0;\n"); }
__device__ __forceinline__ void cpwait1()  { asm volatile("cp.async.wait_group 1;\n"); }

// ---------------- epilogue (shared by both tiles) ----------------
__device__ __forceinline__ void epi_store(
    float v0, float v1, float* C, int N, int r_, int cc0, int act)
{
    if (act == 0) {
        *(float2*)(C + (long)r_ * N + cc0) = make_float2(v0, v1);
    } else if (act == 1) {
        *(float2*)(C + (long)r_ * N + cc0) = make_float2(fmaxf(v0, 0.f), fmaxf(v1, 0.f));
    } else if (act == 4) {
        __half2 h = __floats2half2_rn(v0, v1);
        *(__half2*)((__half*)C + (long)r_ * N + cc0) = h;
    } else if (act == 5) {          // hT: [b][c][n]
        __half* CT = (__half*)C;
        int b_ = r_ >> 10, j = r_ & 1023;
        CT[((long)(b_ * CHID + cc0))     * CN + j] = __float2half_rn(v0);
        CT[((long)(b_ * CHID + cc0 + 1)) * CN + j] = __float2half_rn(v1);
    } else {                        // 6: VT: [bh][d][j]
        __half* CT = (__half*)C;
        int bh = r_ >> 8;
        int j = ((r_ & 255) << 2) | (cc0 >> 6);
        int d = cc0 & 63;
        long base = ((long)bh << 16) + ((long)d << 10) + j;
        CT[base] = __float2half_rn(v0);
        CT[base + 1024] = __float2half_rn(v1);
    }
}

// ---------------- weight transpose+fp16 pack ----------------
struct W8 { const float* src[8]; };
__global__ void wpack8_kernel(W8 w, __half* dst)
{
    __shared__ float tile[32][33];
    int mi = blockIdx.z;
    const float* W = w.src[mi];
    __half* WT = dst + (long)mi * CHID * CHID;
    int k0 = blockIdx.x * 32, n0 = blockIdx.y * 32;
    int tx = threadIdx.x & 31, ty = threadIdx.x >> 5;
    #pragma unroll
    for (int i = 0; i < 32; i += 8)
        tile[ty + i][tx] = W[(long)(k0 + ty + i) * CHID + n0 + tx];
    __syncthreads();
    #pragma unroll
    for (int i = 0; i < 32; i += 8)
        WT[(long)(n0 + ty + i) * CHID + k0 + tx] = __float2half_rn(tile[tx][ty + i]);
}
__global__ void wpack_fc1_kernel(const float* __restrict__ W, __half* __restrict__ WT)
{
    __shared__ float tile[32][33];
    int k0 = blockIdx.x * 32, n0 = blockIdx.y * 32;
    int tx = threadIdx.x & 31, ty = threadIdx.x >> 5;
    #pragma unroll
    for (int i = 0; i < 32; i += 8)
        tile[ty + i][tx] = W[(long)(k0 + ty + i) * CHID + n0 + tx];
    __syncthreads();
    #pragma unroll
    for (int i = 0; i < 32; i += 8)
        WT[(long)(n0 + ty + i) * CDIN + k0 + tx] = __float2half_rn(tile[tx][ty + i]);
}

// ================= fp16 GEMM tile 128x128 (pairs; grid>=256) =================
struct TileCtx {
    float *As; __half *Bs;
    uint32_t As_b, Bs_b;
    const float *Ag; const __half *Bg;
    int K, N;
    int tid;
};
constexpr int T_strA = 36;
constexpr int T_strB = 40;
constexpr int T_AW = 128 * T_strA;
constexpr int T_BW = 128 * T_strB;
constexpr int SM_TG = 2 * (T_AW * 4 + T_BW * 2);   // 57344 bytes

__device__ __forceinline__ void tg_load_stage(TileCtx& c, int kt, int s) {
    int k0 = kt * 32;
    #pragma unroll
    for (int i = 0; i < 4; i++) {
        int f = c.tid + i * 256;
        int m = f >> 3, k4 = (f & 7) * 4;
        cpasync16(c.As_b + (uint32_t)(((s * 128 + m) * T_strA + k4) * 4),
                  c.Ag + (long)m * c.K + k0 + k4);
    }
    #pragma unroll
    for (int i = 0; i < 2; i++) {
        int f = c.tid + i * 256;
        int n = f >> 2, c8 = (f & 3) * 8;
        cpasync16(c.Bs_b + (uint32_t)(((s * 128 + n) * T_strB + c8) * 2),
                  c.Bg + (long)n * c.K + k0 + c8);
    }
    cpcommit();
}

__device__ __forceinline__ void tg_body(
    TileCtx& c, const float* bias, float* C, int M, int N, int K,
    int row0, int col0, int act)
{
    int tid  = c.tid;
    int warp = tid >> 5, lane = tid & 31;
    int g = lane >> 2, tg = lane & 3;
    int mw = warp >> 2, nw = warp & 3;

    float acc[4][4][4];
    #pragma unroll
    for (int mi = 0; mi < 4; mi++)
        #pragma unroll
        for (int ni = 0; ni < 4; ni++)
            #pragma unroll
            for (int q = 0; q < 4; q++) acc[mi][ni][q] = 0.f;

    int nk = K / 32;
    tg_load_stage(c, 0, 0);

    for (int kt = 0; kt < nk; kt++) {
        cpwait0();
        __syncthreads();
        int s = kt & 1;
        if (kt + 1 < nk) tg_load_stage(c, kt + 1, s ^ 1);

        const float* Asb = c.As + s * T_AW;
        const __half* Bsb = c.Bs + s * T_BW;
        #pragma unroll
        for (int ks = 0; ks < 32; ks += 16) {
            uint32_t a[4][4], b[4][2];
            #pragma unroll
            for (int mi = 0; mi < 4; mi++) {
                int mr = mw * 64 + mi * 16;
                const float* r0p = &Asb[(mr + g)     * T_strA + ks + 2 * tg];
                const float* r1p = &Asb[(mr + g + 8) * T_strA + ks + 2 * tg];
                float2 v0 = *(const float2*)r0p;
                float2 v1 = *(const float2*)r1p;
                float2 v2 = *(const float2*)(r0p + 8);
                float2 v3 = *(const float2*)(r1p + 8);
                a[mi][0] = pkh2(v0.x, v0.y);
                a[mi][1] = pkh2(v1.x, v1.y);
                a[mi][2] = pkh2(v2.x, v2.y);
                a[mi][3] = pkh2(v3.x, v3.y);
            }
            #pragma unroll
            for (int ni = 0; ni < 4; ni++) {
                int nc = nw * 32 + ni * 8;
                const __half* bp = &Bsb[(nc + g) * T_strB + ks + 2 * tg];
                b[ni][0] = *(const uint32_t*)bp;
                b[ni][1] = *(const uint32_t*)(bp + 8);
            }
            #pragma unroll
            for (int mi = 0; mi < 4; mi++)
                #pragma unroll
                for (int ni = 0; ni < 4; ni++)
                    mma_f16(acc[mi][ni], a[mi], b[ni]);
        }
    }

    #pragma unroll
    for (int mi = 0; mi < 4; mi++) {
        #pragma unroll
        for (int ni = 0; ni < 4; ni++) {
            int r = row0 + mw * 64 + mi * 16 + g;
            int cc0 = col0 + nw * 32 + ni * 8 + tg * 2;
            float b0 = bias ? bias[cc0] : 0.f;
            float b1 = bias ? bias[cc0 + 1] : 0.f;
            #pragma unroll
            for (int rr = 0; rr < 2; rr++)
                epi_store(acc[mi][ni][rr * 2 + 0] + b0, acc[mi][ni][rr * 2 + 1] + b1,
                          C, N, r + rr * 8, cc0, act);
        }
    }
}

struct G2 { const float* A[2]; const __half* B[2]; const float* bias[2]; float* C[2]; int act[2]; };
__global__ void __launch_bounds__(256, 2) tgemm_pair(G2 args, int M, int N, int K)
{
    extern __shared__ float smem[];
    int z = blockIdx.z;
    TileCtx c;
    c.As = smem; c.Bs = (__half*)(smem + 2 * T_AW);
    c.As_b = (uint32_t)__cvta_generic_to_shared(c.As);
    c.Bs_b = (uint32_t)__cvta_generic_to_shared(c.Bs);
    c.K = K; c.N = N; c.tid = threadIdx.x;
    int row0 = blockIdx.y * 128, col0 = blockIdx.x * 128;
    c.Ag = args.A[z] + (long)row0 * K;
    c.Bg = args.B[z] + (long)col0 * K;
    tg_body(c, args.bias[z], args.C[z], M, N, K, row0, col0, args.act[z]);
}

// ================= fp16 GEMM tile 128x64 (single launches; grid 256) =================
constexpr int T64_BW = 64 * T_strB;                          // halves/stage
constexpr int SM_T64 = 2 * (T_AW * 4 + T64_BW * 2);          // 47104 bytes

template<int ACT>
__global__ void __launch_bounds__(256, 2) tgemm64(
    const float* __restrict__ A, const __half* __restrict__ Bm,
    const float* __restrict__ bias, float* __restrict__ C,
    int M, int N, int K)
{
    extern __shared__ float smem[];
    float* As = smem;
    __half* Bs = (__half*)(smem + 2 * T_AW);
    uint32_t As_b = (uint32_t)__cvta_generic_to_shared(As);
    uint32_t Bs_b = (uint32_t)__cvta_generic_to_shared(Bs);
    int tid = threadIdx.x;
    int row0 = blockIdx.y * 128, col0 = blockIdx.x * 64;
    const float* Ag = A + (long)row0 * K;
    const __half* Bg = Bm + (long)col0 * K;

    int warp = tid >> 5, lane = tid & 31;
    int g = lane >> 2, tg = lane & 3;
    int mw = warp >> 1, nw = warp & 1;          // 4m x 2n, warp tile 32x32

    auto load_stage = [&](int kt, int s) {
        int k0 = kt * 32;
        #pragma unroll
        for (int i = 0; i < 4; i++) {
            int f = tid + i * 256;
            int m = f >> 3, k4 = (f & 7) * 4;
            cpasync16(As_b + (uint32_t)(((s * 128 + m) * T_strA + k4) * 4),
                      Ag + (long)m * K + k0 + k4);
        }
        {
            int n = tid >> 2, c8 = (tid & 3) * 8;
            cpasync16(Bs_b + (uint32_t)(((s * 64 + n) * T_strB + c8) * 2),
                      Bg + (long)n * K + k0 + c8);
        }
        cpcommit();
    };

    float acc[2][4][4];
    #pragma unroll
    for (int mi = 0; mi < 2; mi++)
        #pragma unroll
        for (int ni = 0; ni < 4; ni++)
            #pragma unroll
            for (int q = 0; q < 4; q++) acc[mi][ni][q] = 0.f;

    int nk = K / 32;
    load_stage(0, 0);

    for (int kt = 0; kt < nk; kt++) {
        cpwait0();
        __syncthreads();
        int s = kt & 1;
        if (kt + 1 < nk) load_stage(kt + 1, s ^ 1);

        const float* Asb = As + s * T_AW;
        const __half* Bsb = Bs + s * T64_BW;
        #pragma unroll
        for (int ks = 0; ks < 32; ks += 16) {
            uint32_t a[2][4], b[4][2];
            #pragma unroll
            for (int mi = 0; mi < 2; mi++) {
                int mr = mw * 32 + mi * 16;
                const float* r0p = &Asb[(mr + g)     * T_strA + ks + 2 * tg];
                const float* r1p = &Asb[(mr + g + 8) * T_strA + ks + 2 * tg];
                float2 v0 = *(const float2*)r0p;
                float2 v1 = *(const float2*)r1p;
                float2 v2 = *(const float2*)(r0p + 8);
                float2 v3 = *(const float2*)(r1p + 8);
                a[mi][0] = pkh2(v0.x, v0.y);
                a[mi][1] = pkh2(v1.x, v1.y);
                a[mi][2] = pkh2(v2.x, v2.y);
                a[mi][3] = pkh2(v3.x, v3.y);
            }
            #pragma unroll
            for (int ni = 0; ni < 4; ni++) {
                int nc = nw * 32 + ni * 8;
                const __half* bp = &Bsb[(nc + g) * T_strB + ks + 2 * tg];
                b[ni][0] = *(const uint32_t*)bp;
                b[ni][1] = *(const uint32_t*)(bp + 8);
            }
            #pragma unroll
            for (int mi = 0; mi < 2; mi++)
                #pragma unroll
                for (int ni = 0; ni < 4; ni++)
                    mma_f16(acc[mi][ni], a[mi], b[ni]);
        }
    }

    #pragma unroll
    for (int mi = 0; mi < 2; mi++) {
        #pragma unroll
        for (int ni = 0; ni < 4; ni++) {
            int r = row0 + mw * 32 + mi * 16 + g;
            int cc0 = col0 + nw * 32 + ni * 8 + tg * 2;
            float b0 = bias ? bias[cc0] : 0.f;
            float b1 = bias ? bias[cc0 + 1] : 0.f;
            #pragma unroll
            for (int rr = 0; rr < 2; rr++)
                epi_store(acc[mi][ni][rr * 2 + 0] + b0, acc[mi][ni][rr * 2 + 1] + b1,
                          C, N, r + rr * 8, cc0, ACT);
        }
    }
}

// ---------------- fp16 flash attention ----------------
constexpr int F_ST = 72;
constexpr int SM_FLASH = (128 * F_ST + 2 * 64 * F_ST + 2 * 64 * F_ST) * 2;  // 55296
__global__ void __launch_bounds__(256, 2) flash_kernel(
    const __half* __restrict__ Q, const __half* __restrict__ Kg_,
    const __half* __restrict__ Vt_, float* __restrict__ O)
{
    constexpr int KT = 64;
    extern __shared__ float smraw[];
    __half* Qs = (__half*)smraw;
    __half* Ks = Qs + 128 * F_ST;
    __half* Vs = Ks + 2 * KT * F_ST;
    uint32_t Qs_b = (uint32_t)__cvta_generic_to_shared(Qs);
    uint32_t Ks_b = (uint32_t)__cvta_generic_to_shared(Ks);
    uint32_t Vs_b = (uint32_t)__cvta_generic_to_shared(Vs);

    int bh = blockIdx.y;
    const __half* Qg = Q + (long)bh * CN * CDH + (long)blockIdx.x * 128 * CDH;
    const __half* Kg = Kg_ + (long)bh * CN * CDH;
    const __half* Vg = Vt_ + ((long)bh << 16);
    float* Og = O + (long)bh * CN * CDH + (long)blockIdx.x * 128 * CDH;

    int tid = threadIdx.x, warp = tid >> 5, lane = tid & 31;
    int g = lane >> 2, tg = lane & 3;
    int r0 = warp * 16;

    #pragma unroll
    for (int i = 0; i < 4; i++) {
        int f = tid + i * 256;
        int r = f >> 3, ch = f & 7;
        cpasync16(Qs_b + (uint32_t)((r * F_ST + ch * 8) * 2), Qg + r * CDH + ch * 8);
    }
    cpcommit();

    auto load_kv = [&](int t, int s) {
        const __half* Kt = Kg + t * KT * CDH;
        const __half* Vtb = Vg + t * KT;
        #pragma unroll
        for (int i = 0; i < 2; i++) {
            int f = tid + i * 256;
            int r = f >> 3, ch = f & 7;
            cpasync16(Ks_b + (uint32_t)(((s * KT + r) * F_ST + ch * 8) * 2),
                      Kt + r * CDH + ch * 8);
        }
        #pragma unroll
        for (int i = 0; i < 2; i++) {
            int f = tid + i * 256;
            int r = f >> 3, ch = f & 7;
            cpasync16(Vs_b + (uint32_t)(((s * KT + r) * F_ST + ch * 8) * 2),
                      Vtb + (long)r * CN + ch * 8);
        }
        cpcommit();
    };
    load_kv(0, 0);

    cpwait1();
    __syncthreads();

    uint32_t aq[4][4];
    #pragma unroll
    for (int kf = 0; kf < 4; kf++) {
        aq[kf][0] = *(uint32_t*)&Qs[(r0 + g)     * F_ST + kf * 16 + 2 * tg];
        aq[kf][1] = *(uint32_t*)&Qs[(r0 + g + 8) * F_ST + kf * 16 + 2 * tg];
        aq[kf][2] = *(uint32_t*)&Qs[(r0 + g)     * F_ST + kf * 16 + 2 * tg + 8];
        aq[kf][3] = *(uint32_t*)&Qs[(r0 + g + 8) * F_ST + kf * 16 + 2 * tg + 8];
    }

    const uint32_t bones[2] = {0x3C003C00u, 0x3C003C00u};
    float m0 = -3.4e38f, m1 = -3.4e38f;
    float lacc[4] = {0.f, 0.f, 0.f, 0.f};
    float o[8][4];
    #pragma unroll
    for (int nf = 0; nf < 8; nf++)
        #pragma unroll
        for (int q = 0; q < 4; q++) o[nf][q] = 0.f;

    for (int t = 0; t < 16; t++) {
        int s = t & 1;
        if (t < 15) load_kv(t + 1, s ^ 1);
        if (t < 15) cpwait1(); else cpwait0();
        __syncthreads();

        float sc[8][4];
        #pragma unroll
        for (int nf = 0; nf < 8; nf++)
            #pragma unroll
            for (int q = 0; q < 4; q++) sc[nf][q] = 0.f;
        #pragma unroll
        for (int kf = 0; kf < 4; kf++) {
            #pragma unroll
            for (int nf = 0; nf < 8; nf++) {
                uint32_t b[2];
                const __half* kr = &Ks[(s * KT + nf * 8 + g) * F_ST + kf * 16 + 2 * tg];
                b[0] = *(uint32_t*)kr;
                b[1] = *(uint32_t*)(kr + 8);
                mma_f16(sc[nf], aq[kf], b);
            }
        }

        float mx0 = -3.4e38f, mx1 = -3.4e38f;
        #pragma unroll
        for (int nf = 0; nf < 8; nf++) {
            mx0 = fmaxf(mx0, fmaxf(sc[nf][0], sc[nf][1]));
            mx1 = fmaxf(mx1, fmaxf(sc[nf][2], sc[nf][3]));
        }
        #pragma unroll
        for (int off = 1; off <= 2; off <<= 1) {
            mx0 = fmaxf(mx0, __shfl_xor_sync(0xffffffffu, mx0, off));
            mx1 = fmaxf(mx1, __shfl_xor_sync(0xffffffffu, mx1, off));
        }
        float mn0 = fmaxf(m0, mx0 * 0.125f);
        float mn1 = fmaxf(m1, mx1 * 0.125f);
        float cr0 = __expf(m0 - mn0);
        float cr1 = __expf(m1 - mn1);
        lacc[0] *= cr0; lacc[1] *= cr0; lacc[2] *= cr1; lacc[3] *= cr1;
        #pragma unroll
        for (int nf = 0; nf < 8; nf++) {
            o[nf][0] *= cr0; o[nf][1] *= cr0;
            o[nf][2] *= cr1; o[nf][3] *= cr1;
        }
        m0 = mn0; m1 = mn1;

        constexpr float CSC = 0.125f * L2EF;
        float mnl0 = mn0 * L2EF, mnl1 = mn1 * L2EF;
        uint32_t ph[8][2];
        #pragma unroll
        for (int nf = 0; nf < 8; nf++) {
            ph[nf][0] = ex2h2(fmaf(sc[nf][0], CSC, -mnl0), fmaf(sc[nf][1], CSC, -mnl0));
            ph[nf][1] = ex2h2(fmaf(sc[nf][2], CSC, -mnl1), fmaf(sc[nf][3], CSC, -mnl1));
        }

        #pragma unroll
        for (int kf = 0; kf < 4; kf++) {
            uint32_t a[4];
            a[0] = ph[2 * kf][0];
            a[1] = ph[2 * kf][1];
            a[2] = ph[2 * kf + 1][0];
            a[3] = ph[2 * kf + 1][1];
            mma_f16(lacc, a, bones);
            #pragma unroll
            for (int nf = 0; nf < 8; nf++) {
                uint32_t b[2];
                const __half* vr = &Vs[(s * KT + nf * 8 + g) * F_ST + kf * 16 + 2 * tg];
                b[0] = *(uint32_t*)vr;
                b[1] = *(uint32_t*)(vr + 8);
                mma_f16(o[nf], a, b);
            }
        }
        __syncthreads();
    }

    float inv0 = 1.f / lacc[0], inv1 = 1.f / lacc[2];
    #pragma unroll
    for (int nf = 0; nf < 8; nf++) {
        int c = nf * 8 + tg * 2;
        *(float2*)(Og + (long)(r0 + g)     * CDH + c) = make_float2(o[nf][0] * inv0, o[nf][1] * inv0);
        *(float2*)(Og + (long)(r0 + g + 8) * CDH + c) = make_float2(o[nf][2] * inv1, o[nf][3] * inv1);
    }
}

// ---------------- pack adj+smask ----------------
__global__ void pack_codes(const int* __restrict__ adj, const int* __restrict__ smask,
                           uint8_t* __restrict__ codes)
{
    long i = (long)blockIdx.x * 256 + threadIdx.x;
    int4 a = ((const int4*)adj)[i];
    int4 s = ((const int4*)smask)[i];
    uchar4 c;
    c.x = (uint8_t)(((a.x > 0) ? 2 : 0) | (s.x & 1));
    c.y = (uint8_t)(((a.y > 0) ? 2 : 0) | (s.y & 1));
    c.z = (uint8_t)(((a.z > 0) ? 2 : 0) | (s.z & 1));
    c.w = (uint8_t)(((a.w > 0) ? 2 : 0) | (s.w & 1));
    ((uchar4*)codes)[i] = c;
}

// ---------------- fused GAT attention ----------------
constexpr int G_CS = 80;
constexpr int SM_GATT = 2 * 64 * F_ST * 2 + CN * 4 + 2 * 128 * G_CS;  // 43008
__global__ void __launch_bounds__(256, 2) gatt_kernel(
    const float* __restrict__ e1, const float* __restrict__ e2,
    const float* __restrict__ rsc, const uint8_t* __restrict__ codes,
    const __half* __restrict__ hT, float* __restrict__ Agg)
{
    constexpr int JT = 64;
    extern __shared__ float smraw[];
    __half* Hs = (__half*)smraw;
    float* e2s = (float*)(Hs + 2 * JT * F_ST);
    uint8_t* Cs = (uint8_t*)(e2s + CN);
    uint32_t Hs_b = (uint32_t)__cvta_generic_to_shared(Hs);
    uint32_t Cs_b = (uint32_t)__cvta_generic_to_shared(Cs);

    int nq = blockIdx.x, ib = blockIdx.y, b = blockIdx.z;
    const __half*  hB  = hT + ((long)(b * CHID + nq * 64)) * CN;
    const uint8_t* cB  = codes + ((long)b * CN + ib * 128) * CN;
    const float*   e2B = e2 + (long)b * CN;
    float* AggB = Agg + ((long)b * CN + ib * 128) * CHID + nq * 64;

    int tid = threadIdx.x, warp = tid >> 5, lane = tid & 31;
    int g = lane >> 2, tg = lane & 3;
    int r0 = warp * 16;

    auto load_jt = [&](int t, int s) {
        #pragma unroll
        for (int i = 0; i < 2; i++) {
            int f = tid + i * 256;
            int r = f >> 3, ch = f & 7;
            cpasync16(Hs_b + (uint32_t)(((s * JT + r) * F_ST + ch * 8) * 2),
                      hB + (long)r * CN + t * JT + ch * 8);
        }
        #pragma unroll
        for (int i = 0; i < 2; i++) {
            int f = tid + i * 256;
            int r = f >> 2, c16 = (f & 3) * 16;
            cpasync16(Cs_b + (uint32_t)(s * 128 * G_CS + r * G_CS + c16),
                      cB + (long)r * CN + t * JT + c16);
        }
        cpcommit();
    };
    load_jt(0, 0);

    ((float4*)e2s)[tid] = ((const float4*)e2B)[tid];
    float e1v0 = e1[(long)b * CN + ib * 128 + r0 + g];
    float e1v1 = e1[(long)b * CN + ib * 128 + r0 + g + 8];
    float rA = rsc[0], rB2 = rsc[1];

    const uint32_t bones[2] = {0x3C003C00u, 0x3C003C00u};
    float m0 = -3.4e38f, m1 = -3.4e38f;
    float lacc[4] = {0.f, 0.f, 0.f, 0.f};
    float o[8][4];
    #pragma unroll
    for (int nf = 0; nf < 8; nf++)
        #pragma unroll
        for (int q = 0; q < 4; q++) o[nf][q] = 0.f;

    for (int t = 0; t < 16; t++) {
        int s = t & 1;
        if (t < 15) load_jt(t + 1, s ^ 1);
        if (t < 15) cpwait1(); else cpwait0();
        __syncthreads();

        float sc[8][4];
        #pragma unroll
        for (int nf = 0; nf < 8; nf++) {
            int lc = nf * 8 + tg * 2;
            float eA = e2s[t * JT + lc];
            float eB = e2s[t * JT + lc + 1];
            uint32_t c0 = *(const uint16_t*)&Cs[s * 128 * G_CS + (r0 + g) * G_CS + lc];
            uint32_t c1 = *(const uint16_t*)&Cs[s * 128 * G_CS + (r0 + g + 8) * G_CS + lc];
            float v;
            v = e1v0 + eA + ((c0 & 1u)   ? rB2 : rA); v = v >= 0.f ? v : ALPHAF * v; sc[nf][0] = (c0 & 2u)   ? v : NEGF;
            v = e1v0 + eB + ((c0 & 256u) ? rB2 : rA); v = v >= 0.f ? v : ALPHAF * v; sc[nf][1] = (c0 & 512u) ? v : NEGF;
            v = e1v1 + eA + ((c1 & 1u)   ? rB2 : rA); v = v >= 0.f ? v : ALPHAF * v; sc[nf][2] = (c1 & 2u)   ? v : NEGF;
            v = e1v1 + eB + ((c1 & 256u) ? rB2 : rA); v = v >= 0.f ? v : ALPHAF * v; sc[nf][3] = (c1 & 512u) ? v : NEGF;
        }

        float mx0 = -3.4e38f, mx1 = -3.4e38f;
        #pragma unroll
        for (int nf = 0; nf < 8; nf++) {
            mx0 = fmaxf(mx0, fmaxf(sc[nf][0], sc[nf][1]));
            mx1 = fmaxf(mx1, fmaxf(sc[nf][2], sc[nf][3]));
        }
        #pragma unroll
        for (int off = 1; off <= 2; off <<= 1) {
            mx0 = fmaxf(mx0, __shfl_xor_sync(0xffffffffu, mx0, off));
            mx1 = fmaxf(mx1, __shfl_xor_sync(0xffffffffu, mx1, off));
        }
        float mn0 = fmaxf(m0, mx0);
        float mn1 = fmaxf(m1, mx1);
        float cr0 = __expf(m0 - mn0);
        float cr1 = __expf(m1 - mn1);
        lacc[0] *= cr0; lacc[1] *= cr0; lacc[2] *= cr1; lacc[3] *= cr1;
        #pragma unroll
        for (int nf = 0; nf < 8; nf++) {
            o[nf][0] *= cr0; o[nf][1] *= cr0;
            o[nf][2] *= cr1; o[nf][3] *= cr1;
        }
        m0 = mn0; m1 = mn1;

        float mnl0 = mn0 * L2EF, mnl1 = mn1 * L2EF;
        uint32_t ph[8][2];
        #pragma unroll
        for (int nf = 0; nf < 8; nf++) {
            ph[nf][0] = ex2h2(fmaf(sc[nf][0], L2EF, -mnl0), fmaf(sc[nf][1], L2EF, -mnl0));
            ph[nf][1] = ex2h2(fmaf(sc[nf][2], L2EF, -mnl1), fmaf(sc[nf][3], L2EF, -mnl1));
        }

        #pragma unroll
        for (int kf = 0; kf < 4; kf++) {
            uint32_t a[4];
            a[0] = ph[2 * kf][0];
            a[1] = ph[2 * kf][1];
            a[2] = ph[2 * kf + 1][0];
            a[3] = ph[2 * kf + 1][1];
            mma_f16(lacc, a, bones);
            #pragma unroll
            for (int nf = 0; nf < 8; nf++) {
                uint32_t b2[2];
                const __half* hr = &Hs[(s * JT + nf * 8 + g) * F_ST + kf * 16 + 2 * tg];
                b2[0] = *(uint32_t*)hr;
                b2[1] = *(uint32_t*)(hr + 8);
                mma_f16(o[nf], a, b2);
            }
        }
        __syncthreads();
    }

    float inv0 = 1.f / lacc[0], inv1 = 1.f / lacc[2];
    #pragma unroll
    for (int nf = 0; nf < 8; nf++) {
        int c = nf * 8 + tg * 2;
        float v0 = o[nf][0] * inv0, v1 = o[nf][1] * inv0;
        float v2 = o[nf][2] * inv1, v3 = o[nf][3] * inv1;
        v0 = v0 > 0.f ? v0 : expm1f(v0);
        v1 = v1 > 0.f ? v1 : expm1f(v1);
        v2 = v2 > 0.f ? v2 : expm1f(v2);
        v3 = v3 > 0.f ? v3 : expm1f(v3);
        *(float2*)(AggB + (long)(r0 + g)     * CHID + c) = make_float2(v0, v1);
        *(float2*)(AggB + (long)(r0 + g + 8) * CHID + c) = make_float2(v2, v3);
    }
}

// ---------------- fp32 tiled SGEMM (fc2 only) ----------------
template<int ACT>
__global__ void sgemm(const float* __restrict__ A, const float* __restrict__ Bm,
                      const float* __restrict__ bias, float* __restrict__ C,
                      int M, int N, int K)
{
    __shared__ float As[16][68];
    __shared__ float Bs[16][68];
    int tx = threadIdx.x;
    int tr = tx >> 4, tc = tx & 15;
    int row0 = blockIdx.y * 64, col0 = blockIdx.x * 64;

    float acc[4][4] = {};
    for (int k0 = 0; k0 < K; k0 += 16) {
        #pragma unroll
        for (int i = 0; i < 4; i++) {
            int idx = tx * 4 + i;
            int m = idx >> 4, k = idx & 15;
            int gr = row0 + m;
            As[k][m] = (gr < M) ? A[(long)gr * K + k0 + k] : 0.f;
        }
        #pragma unroll
        for (int i = 0; i < 4; i++) {
            int idx = tx * 4 + i;
            int k = idx >> 6, n = idx & 63;
            int gn = col0 + n;
            Bs[k][n] = (gn < N) ? Bm[(long)(k0 + k) * N + gn] : 0.f;
        }
        __syncthreads();
        #pragma unroll
        for (int k = 0; k < 16; k++) {
            float a[4], b[4];
            #pragma unroll
            for (int i = 0; i < 4; i++) a[i] = As[k][tr * 4 + i];
            #pragma unroll
            for (int j = 0; j < 4; j++) b[j] = Bs[k][tc * 4 + j];
            #pragma unroll
            for (int i = 0; i < 4; i++)
                #pragma unroll
                for (int j = 0; j < 4; j++)
                    acc[i][j] = fmaf(a[i], b[j], acc[i][j]);
        }
        __syncthreads();
    }
    #pragma unroll
    for (int i = 0; i < 4; i++) {
        int gr = row0 + tr * 4 + i;
        if (gr >= M) continue;
        #pragma unroll
        for (int j = 0; j < 4; j++) {
            int gn = col0 + tc * 4 + j;
            if (gn >= N) continue;
            float v = acc[i][j];
            if (bias) v += bias[gn];
            if (ACT == 1) v = v > 0.f ? v : 0.f;
            C[(long)gr * N + gn] = v;
        }
    }
}

// ---------------- logits ----------------
__global__ void logits_kernel(const float* __restrict__ H, const float* __restrict__ W,
                              const float* __restrict__ bb, float* __restrict__ out)
{
    int warp = threadIdx.x >> 5, lane = threadIdx.x & 31;
    int row = blockIdx.x * 8 + warp;
    float hv[8];
    #pragma unroll
    for (int j = 0; j < 8; j++) hv[j] = H[(long)row * CHID + j * 32 + lane];
    float acc[CNC];
    #pragma unroll
    for (int c = 0; c < CNC; c++) {
        float a = 0.f;
        #pragma unroll
        for (int j = 0; j < 8; j++) a = fmaf(hv[j], W[(j * 32 + lane) * CNC + c], a);
        acc[c] = a;
    }
    #pragma unroll
    for (int c = 0; c < CNC; c++)
        #pragma unroll
        for (int off = 16; off > 0; off >>= 1)
            acc[c] += __shfl_xor_sync(0xffffffffu, acc[c], off);
    if (lane < CNC) out[(long)row * CNC + lane] = acc[lane] + bb[lane];
}

// ---------------- PW = P @ wk ----------------
__global__ void pwk_kernel(const float* __restrict__ P, const float* __restrict__ wk,
                           float* __restrict__ PW)
{
    __shared__ float red[4][64];
    int r = blockIdx.x, dq = blockIdx.y;
    int dloc = threadIdx.x & 63, part = threadIdx.x >> 6;
    int d = dq * 64 + dloc;
    const float* Pr = P + (long)r * CHID;
    float a0 = 0.f, a1 = 0.f, a2 = 0.f, a3 = 0.f;
    int k0 = part * 64;
    #pragma unroll 4
    for (int k = 0; k < 64; k += 4) {
        a0 = fmaf(Pr[k0 + k],     wk[(k0 + k)     * CHID + d], a0);
        a1 = fmaf(Pr[k0 + k + 1], wk[(k0 + k + 1) * CHID + d], a1);
        a2 = fmaf(Pr[k0 + k + 2], wk[(k0 + k + 2) * CHID + d], a2);
        a3 = fmaf(Pr[k0 + k + 3], wk[(k0 + k + 3) * CHID + d], a3);
    }
    red[part][dloc] = (a0 + a1) + (a2 + a3);
    __syncthreads();
    if (part == 0)
        PW[(long)r * CHID + d] = red[0][dloc] + red[1][dloc] + red[2][dloc] + red[3][dloc];
}

// ---------------- Kh ----------------
__global__ void kcomb_kernel(const float* __restrict__ sadj, const float* __restrict__ PW,
                             const float* __restrict__ bk, __half* __restrict__ Kh)
{
    long idx = (long)blockIdx.x * 256 + threadIdx.x;
    int d = idx & (CHID - 1);
    int n = (idx >> 8) & (CN - 1);
    int b = (int)(idx >> 18);
    const float* sa = sadj + (long)b * CM * CN + n;
    const float* Pb = PW + (long)b * CM * CHID + d;
    float acc = bk[d];
    #pragma unroll
    for (int m = 0; m < CM; m++) acc = fmaf(sa[m * CN], Pb[m * CHID], acc);
    Kh[idx] = __float2half_rn(acc);
}

// ---------------- e1/e2 dots ----------------
__global__ void dots_kernel(const __half* __restrict__ hT, const float* __restrict__ a1,
                            const float* __restrict__ a2,
                            float* __restrict__ e1, float* __restrict__ e2)
{
    __shared__ float s1[4][64], s2[4][64];
    int bI = blockIdx.x;
    int b = bI >> 4, jb = bI & 15;
    int jloc = threadIdx.x & 63, part = threadIdx.x >> 6;
    int j = jb * 64 + jloc;
    const __half* base = hT + (long)b * CHID * CN + j;
    float t1 = 0.f, t2 = 0.f;
    #pragma unroll 8
    for (int c = part * 64; c < part * 64 + 64; c++) {
        float v = __half2float(base[(long)c * CN]);
        t1 = fmaf(v, a1[c], t1);
        t2 = fmaf(v, a2[c], t2);
    }
    s1[part][jloc] = t1; s2[part][jloc] = t2;
    __syncthreads();
    if (part == 0) {
        e1[b * CN + j] = s1[0][jloc] + s1[1][jloc] + s1[2][jloc] + s1[3][jloc];
        e2[b * CN + j] = s2[0][jloc] + s2[1][jloc] + s2[2][jloc] + s2[3][jloc];
    }
}

// ---------------- rel_sc ----------------
__global__ void relsc_kernel(const float* __restrict__ rel, const float* __restrict__ a3,
                             float* __restrict__ out)
{
    __shared__ float s[256];
    int r = blockIdx.x, t = threadIdx.x;
    s[t] = rel[r * CHID + t] * a3[t];
    __syncthreads();
    for (int o = 128; o > 0; o >>= 1) {
        if (t < o) s[t] += s[t + o];
        __syncthreads();
    }
    if (t == 0) out[r] = s[0];
}

// ---------------- LayerNorm ----------------
__global__ void ln_kernel(const float* __restrict__ T, const float* __restrict__ Hold,
                          const float* __restrict__ g, const float* __restrict__ bb,
                          float* __restrict__ out)
{
    int warp = threadIdx.x >> 5, lane = threadIdx.x & 31;
    int row = blockIdx.x * 8 + warp;
    long base = (long)row * CHID;
    float v[8];
    float s = 0.f;
    #pragma unroll
    for (int j = 0; j < 8; j++) {
        int c = j * 32 + lane;
        v[j] = T[base + c] + Hold[base + c];
        s += v[j];
    }
    #pragma unroll
    for (int off = 16; off > 0; off >>= 1) s += __shfl_xor_sync(0xffffffffu, s, off);
    float mu = s * (1.f / CHID);
    float q = 0.f;
    #pragma unroll
    for (int j = 0; j < 8; j++) { v[j] -= mu; q = fmaf(v[j], v[j], q); }
    #pragma unroll
    for (int off = 16; off > 0; off >>= 1) q += __shfl_xor_sync(0xffffffffu, q, off);
    float rstd = rsqrtf(q * (1.f / CHID) + 1e-5f);
    #pragma unroll
    for (int j = 0; j < 8; j++) {
        int c = j * 32 + lane;
        out[base + c] = v[j] * rstd * g[c] + bb[c];
    }
}

// ---------------- Pagg partials ----------------
__global__ void pagg_part_kernel(const float* __restrict__ sadj, const float* __restrict__ Hcur,
                                 float* __restrict__ PaggP)
{
    int bm = blockIdx.x, part = blockIdx.y;
    int b = bm >> 3;
    int c = threadIdx.x;
    const float* sa = sadj + (long)bm * CN + part * 256;
    const float* Hb = Hcur + ((long)b * CN + part * 256) * CHID + c;
    float a0 = 0.f, a1 = 0.f, a2 = 0.f, a3 = 0.f;
    #pragma unroll 4
    for (int n = 0; n < 256; n += 4) {
        a0 = fmaf(sa[n],     Hb[(long)(n)     * CHID], a0);
        a1 = fmaf(sa[n + 1], Hb[(long)(n + 1) * CHID], a1);
        a2 = fmaf(sa[n + 2], Hb[(long)(n + 2) * CHID], a2);
        a3 = fmaf(sa[n + 3], Hb[(long)(n + 3) * CHID], a3);
    }
    PaggP[((long)part * 64 + bm) * CHID + c] = (a0 + a1) + (a2 + a3);
}

// ---------------- GRU ----------------
__global__ void gru_kernel(const float* __restrict__ PaggP, float* __restrict__ P,
                           float* __restrict__ Pnew,
                           const float* __restrict__ wz, const float* __restrict__ uz,
                           const float* __restrict__ wr, const float* __restrict__ ur,
                           const float* __restrict__ w,  const float* __restrict__ u)
{
    __shared__ float sp[CHID], sq[CHID];
    __shared__ float red[6][4][64];
    int bm = blockIdx.x, dq = blockIdx.y;
    int dloc = threadIdx.x & 63, part = threadIdx.x >> 6;
    int d = dq * 64 + dloc;
    sp[threadIdx.x] = P[(long)bm * CHID + threadIdx.x];
    sq[threadIdx.x] = PaggP[(long)bm * CHID + threadIdx.x]
                    + PaggP[((long)64 + bm) * CHID + threadIdx.x]
                    + PaggP[((long)128 + bm) * CHID + threadIdx.x]
                    + PaggP[((long)192 + bm) * CHID + threadIdx.x];
    __syncthreads();
    float az = 0, bz = 0, ar = 0, br = 0, aw = 0, bw = 0;
    int k0 = part * 64;
    #pragma unroll 4
    for (int k = k0; k < k0 + 64; k++) {
        float pk = sp[k], qk = sq[k];
        az = fmaf(pk, wz[k * CHID + d], az); bz = fmaf(qk, uz[k * CHID + d], bz);
        ar = fmaf(pk, wr[k * CHID + d], ar); br = fmaf(qk, ur[k * CHID + d], br);
        aw = fmaf(pk, w [k * CHID + d], aw); bw = fmaf(qk, u [k * CHID + d], bw);
    }
    red[0][part][dloc] = az; red[1][part][dloc] = bz;
    red[2][part][dloc] = ar; red[3][part][dloc] = br;
    red[4][part][dloc] = aw; red[5][part][dloc] = bw;
    __syncthreads();
    if (part == 0) {
        float tz = red[0][0][dloc] + red[0][1][dloc] + red[0][2][dloc] + red[0][3][dloc]
                 + red[1][0][dloc] + red[1][1][dloc] + red[1][2][dloc] + red[1][3][dloc];
        float tr_ = red[2][0][dloc] + red[2][1][dloc] + red[2][2][dloc] + red[2][3][dloc]
                  + red[3][0][dloc] + red[3][1][dloc] + red[3][2][dloc] + red[3][3][dloc];
        float tw = red[4][0][dloc] + red[4][1][dloc] + red[4][2][dloc] + red[4][3][dloc];
        float tu = red[5][0][dloc] + red[5][1][dloc] + red[5][2][dloc] + red[5][3][dloc];
        float z  = 1.f / (1.f + expf(-tz));
        float rr = 1.f / (1.f + expf(-tr_));
        float hh = tanhf(tw + rr * tu);
        Pnew[(long)bm * CHID + d] = (1.f - z) * sp[d] + z * hh;
    }
}

// ---------------- p_sim ----------------
__global__ void psim_kernel(const float* __restrict__ P, float* __restrict__ outp, int tail)
{
    __shared__ float red[64];
    int t = threadIdx.x;
    int b = t >> 3, m = t & 7;
    const float* Pb = P + (long)b * CM * CHID;
    float s = 0.f;
    for (int k2 = 0; k2 < CM; k2++) {
        if (k2 == m) continue;
        float d = 0.f;
        for (int dd = 0; dd < CHID; dd++)
            d = fmaf(Pb[m * CHID + dd], Pb[k2 * CHID + dd], d);
        s += d;
    }
    red[t] = s; __syncthreads();
    if ((t & 7) < 4) red[t] += red[t + 4]; __syncthreads();
    if ((t & 7) < 2) red[t] += red[t + 2]; __syncthreads();
    if ((t & 7) < 1) red[t] += red[t + 1]; __syncthreads();
    if (tail >= CB) {
        if (t < CB) outp[t] = red[t * 8] / (float)(CM * CM);
    } else {
        if (t == 0) {
            float tot = 0.f;
            for (int b2 = 0; b2 < CB; b2++) tot += red[b2 * 8];
            outp[0] = tot / (float)(CB * CM * CM);
        }
    }
}

// ---------------- host orchestration ----------------
extern "C" void kernel_launch(void* const* d_in, const int* in_sizes, int n_in,
                              void* d_out, int out_size)
{
    const float* x     = (const float*)d_in[0];
    const int*   adj   = (const int*)  d_in[1];
    const int*   smask = (const int*)  d_in[2];
    const float* sf    = (const float*)d_in[3];
    const float* sadj  = (const float*)d_in[4];
    const float* fc1w  = (const float*)d_in[6];
    const float* fc1b  = (const float*)d_in[7];
    const float* fc2w  = (const float*)d_in[8];
    const float* fc2b  = (const float*)d_in[9];
    const float* gatW  = (const float*)d_in[10];
    const float* gata  = (const float*)d_in[11];
    const float* rel   = (const float*)d_in[12];
    const float* gwz   = (const float*)d_in[13];
    const float* guz   = (const float*)d_in[14];
    const float* gwr   = (const float*)d_in[15];
    const float* gur   = (const float*)d_in[16];
    const float* gw    = (const float*)d_in[17];
    const float* gu    = (const float*)d_in[18];
    const float* wv    = (const float*)d_in[19];
    const float* bv    = (const float*)d_in[20];
    const float* wk    = (const float*)d_in[21];
    const float* bk    = (const float*)d_in[22];
    const float* wq    = (const float*)d_in[23];
    const float* bq    = (const float*)d_in[24];
    const float* wo    = (const float*)d_in[25];
    const float* bo    = (const float*)d_in[26];
    const float* lng   = (const float*)d_in[27];
    const float* lnb   = (const float*)d_in[28];
    const float* outw  = (const float*)d_in[29];
    const float* outb  = (const float*)d_in[30];
    float* out = (float*)d_out;

    float *H, *Hn, *P, *PW, *PaggP, *Agg, *ctx, *Tb, *e1, *e2, *rsc;
    __half *Qh, *Kh, *VT, *hT, *WT8, *WTfc1;
    uint8_t* codes;
    cudaGetSymbolAddress((void**)&H,    g_H);
    cudaGetSymbolAddress((void**)&Hn,   g_Hn);
    cudaGetSymbolAddress((void**)&P,    g_P);
    cudaGetSymbolAddress((void**)&PW,   g_PW);
    cudaGetSymbolAddress((void**)&PaggP, g_PaggP);
    cudaGetSymbolAddress((void**)&Agg,  g_Agg);
    cudaGetSymbolAddress((void**)&ctx,  g_ctx);
    cudaGetSymbolAddress((void**)&Tb,   g_T);
    cudaGetSymbolAddress((void**)&Qh,   g_Qh);
    cudaGetSymbolAddress((void**)&Kh,   g_Kh);
    cudaGetSymbolAddress((void**)&VT,   g_VT);
    cudaGetSymbolAddress((void**)&hT,   g_hT);
    cudaGetSymbolAddress((void**)&WT8,  g_WT8);
    cudaGetSymbolAddress((void**)&WTfc1, g_WTfc1);
    cudaGetSymbolAddress((void**)&codes, g_codes);
    cudaGetSymbolAddress((void**)&e1,   g_e1);
    cudaGetSymbolAddress((void**)&e2,   g_e2);
    cudaGetSymbolAddress((void**)&rsc,  g_rsc);

    cudaFuncSetAttribute(tgemm_pair, cudaFuncAttributeMaxDynamicSharedMemorySize, SM_TG);
    cudaFuncSetAttribute(tgemm64<0>, cudaFuncAttributeMaxDynamicSharedMemorySize, SM_T64);
    cudaFuncSetAttribute(tgemm64<1>, cudaFuncAttributeMaxDynamicSharedMemorySize, SM_T64);
    cudaFuncSetAttribute(tgemm64<4>, cudaFuncAttributeMaxDynamicSharedMemorySize, SM_T64);
    cudaFuncSetAttribute(flash_kernel, cudaFuncAttributeMaxDynamicSharedMemorySize, SM_FLASH);
    cudaFuncSetAttribute(gatt_kernel, cudaFuncAttributeMaxDynamicSharedMemorySize, SM_GATT);

    dim3 blk(256);
    const int BN = CB * CN;
    const long HH = (long)CHID * CHID;
    const long WQ = (long)CHID * CHID;

    // ---- pack weights to fp16 [N][K] (idx = l*4 + {gatW, wv, wq, wo}) ----
    {
        W8 w;
        for (int l = 0; l < 2; l++) {
            w.src[l * 4 + 0] = gatW + l * HH;
            w.src[l * 4 + 1] = wv + l * HH;
            w.src[l * 4 + 2] = wq + l * HH;
            w.src[l * 4 + 3] = wo + l * HH;
        }
        wpack8_kernel<<<dim3(8, 8, 8), blk>>>(w, WT8);
        wpack_fc1_kernel<<<dim3(32, 8), blk>>>(fc1w, WTfc1);
    }

    pack_codes<<<(int)((long)CB * CN * CN / 4 / 256), blk>>>(adj, smask, codes);
    // H = relu(x @ fc1_w + b)  (TN=64 tile: 256 CTAs)
    tgemm64<1><<<dim3(4, 64), blk, SM_T64>>>(x, WTfc1, fc1b, H, BN, CHID, CDIN);
    sgemm<1><<<dim3(4, 1, 1), blk>>>(sf, fc2w, fc2b, P, CB * CM, CHID, CDIN);

    for (int l = 0; l < CL; l++) {
        float* cur = l ? Hn : H;
        float* nxt = l ? H : Hn;

        pwk_kernel<<<dim3(CB * CM, 4), blk>>>(P, wk + l * HH, PW);
        kcomb_kernel<<<BN * CHID / 256, blk>>>(sadj, PW, bk + l * CHID, Kh);

        // paired: hT = (cur @ gatW)^T fp16 ; VT = (cur @ wv + bv) head-T fp16
        {
            G2 a;
            a.A[0] = cur;                  a.A[1] = cur;
            a.B[0] = WT8 + (l * 4 + 0) * WQ; a.B[1] = WT8 + (l * 4 + 1) * WQ;
            a.bias[0] = nullptr;           a.bias[1] = bv + l * CHID;
            a.C[0] = (float*)hT;           a.C[1] = (float*)VT;
            a.act[0] = 5;                  a.act[1] = 6;
            tgemm_pair<<<dim3(2, 64, 2), blk, SM_TG>>>(a, BN, CHID, CHID);
        }
        dots_kernel<<<CB * 16, blk>>>(hT, gata + l * 3 * CHID, gata + l * 3 * CHID + CHID, e1, e2);
        relsc_kernel<<<2, blk>>>(rel + l * 2 * CHID, gata + l * 3 * CHID + 2 * CHID, rsc);
        gatt_kernel<<<dim3(4, 8, CB), blk, SM_GATT>>>(e1, e2, rsc, codes, hT, Agg);
        // Qh = Agg @ wq + bq (TN=64)
        tgemm64<4><<<dim3(4, 64), blk, SM_T64>>>(Agg, WT8 + (l * 4 + 2) * WQ, bq + l * CHID,
                                                 (float*)Qh, BN, CHID, CHID);
        flash_kernel<<<dim3(8, 32), blk, SM_FLASH>>>(Qh, Kh, VT, ctx);
        // Tb = ctx @ wo + bo (TN=64)
        tgemm64<0><<<dim3(4, 64), blk, SM_T64>>>(ctx, WT8 + (l * 4 + 3) * WQ, bo + l * CHID,
                                                 Tb, BN, CHID, CHID);
        ln_kernel<<<BN / 8, blk>>>(Tb, cur, lng + l * CHID, lnb + l * CHID, nxt);

        pagg_part_kernel<<<dim3(CB * CM, 4), blk>>>(sadj, cur, PaggP);
        gru_kernel<<<dim3(CB * CM, 4), blk>>>(PaggP, P, P,
                                              gwz + l * HH, guz + l * HH,
                                              gwr + l * HH, gur + l * HH,
                                              gw + l * HH,  gu + l * HH);
    }

    logits_kernel<<<BN / 8, blk>>>(H, outw, outb, out);
    psim_kernel<<<1, 64>>>(P, out + (long)BN * CNC, out_size - BN * CNC);
}